// round 3
// baseline (speedup 1.0000x reference)
#include <cuda_runtime.h>
#include <cstdint>

#define BB 24
#define DD 128
#define NN 2048
#define MM 2048
#define KC 32

// ---------------- scratch (device globals; no runtime allocation) ----------
__device__ float g_S [(size_t)BB * NN * MM];   // 402 MB: S = st + sc + sq
__device__ float g_A [(size_t)BB * DD * NN];   // A  = Q @ S1^T
__device__ float g_U [(size_t)BB * DD * MM];   // U  = C @ S2
__device__ float g_Bt[(size_t)BB * DD * NN];   // Bt = U @ S1^T
__device__ float g_sq  [BB * MM];
__device__ float g_sc  [BB * NN];
__device__ float g_rmax[BB * NN];
__device__ float g_rinv[BB * NN];
__device__ float g_cmax[BB * MM];
__device__ float g_cinv[BB * MM];

// ---------------- threefry2x32 (bit-exact replay of jax.random key(42)) ----
__device__ __forceinline__ void tf_round(uint32_t& x0, uint32_t& x1, int r) {
    x0 += x1;
    x1 = (x1 << r) | (x1 >> (32 - r));
    x1 ^= x0;
}

__device__ __forceinline__ uint2 threefry_0_42(uint32_t c0, uint32_t c1) {
    const uint32_t ks0 = 0u, ks1 = 42u, ks2 = 0x1BD11BDAu ^ 0u ^ 42u;
    uint32_t x0 = c0 + ks0, x1 = c1 + ks1;
    tf_round(x0, x1, 13); tf_round(x0, x1, 15); tf_round(x0, x1, 26); tf_round(x0, x1, 6);
    x0 += ks1; x1 += ks2 + 1u;
    tf_round(x0, x1, 17); tf_round(x0, x1, 29); tf_round(x0, x1, 16); tf_round(x0, x1, 24);
    x0 += ks2; x1 += ks0 + 2u;
    tf_round(x0, x1, 13); tf_round(x0, x1, 15); tf_round(x0, x1, 26); tf_round(x0, x1, 6);
    x0 += ks0; x1 += ks1 + 3u;
    tf_round(x0, x1, 17); tf_round(x0, x1, 29); tf_round(x0, x1, 16); tf_round(x0, x1, 24);
    x0 += ks1; x1 += ks2 + 4u;
    tf_round(x0, x1, 13); tf_round(x0, x1, 15); tf_round(x0, x1, 26); tf_round(x0, x1, 6);
    x0 += ks2; x1 += ks0 + 5u;
    return make_uint2(x0, x1);
}

__device__ __forceinline__ float apply_drop(uint32_t bits, float v) {
    // jax uniform: bitcast(bits>>9 | 0x3f800000) - 1.0 ; keep = u < 0.9f
    float u = __uint_as_float((bits >> 9) | 0x3f800000u) - 1.0f;
    return (u < 0.9f) ? v * (1.0f / 0.9f) : 0.0f;
}

// ---------------- kernel 1: sq[b,m] = Wq.Q ; sc[b,n] = Wc.C -----------------
__global__ __launch_bounds__(256) void wsum_kernel(const float* __restrict__ Q,
                                                   const float* __restrict__ C,
                                                   const float* __restrict__ W) {
    int b = blockIdx.y;
    int which = blockIdx.z;            // 0: sq from Q, 1: sc from C
    int m = blockIdx.x * 256 + threadIdx.x;
    const float* X = which ? C : Q;
    const float* w = W + b * (3 * DD) + (which ? DD : 0);
    const float* xb = X + (size_t)b * DD * MM + m;
    float s = 0.f;
#pragma unroll 8
    for (int d = 0; d < DD; d++) s += w[d] * xb[(size_t)d * MM];
    if (which) g_sc[b * NN + m] = s;
    else       g_sq[b * MM + m] = s;
}

// ---------------- kernel 2: S[b,n,m] = sum_d C*Wm*Q + sc[n] + sq[m] ---------
__global__ __launch_bounds__(256) void gemm_S_kernel(const float* __restrict__ C,
                                                     const float* __restrict__ Q,
                                                     const float* __restrict__ W) {
    __shared__ float Cs[64][KC + 1];
    __shared__ float Qs[64][KC + 1];
    __shared__ float wm[DD];
    int b  = blockIdx.z;
    int n0 = blockIdx.y * 64;
    int m0 = blockIdx.x * 64;
    int tid = threadIdx.x;
    if (tid < DD) wm[tid] = W[b * (3 * DD) + 2 * DD + tid];
    __syncthreads();
    int tx = tid & 15, ty = tid >> 4;
    float acc[4][4] = {};
    const float* Cb = C + (size_t)b * DD * NN;
    const float* Qb = Q + (size_t)b * DD * MM;

    for (int d0 = 0; d0 < DD; d0 += KC) {
#pragma unroll
        for (int it = 0; it < 8; it++) {
            int idx = tid + it * 256;
            int dj = idx >> 6, i = idx & 63;
            Cs[i][dj] = Cb[(size_t)(d0 + dj) * NN + n0 + i] * wm[d0 + dj];
            Qs[i][dj] = Qb[(size_t)(d0 + dj) * MM + m0 + i];
        }
        __syncthreads();
#pragma unroll
        for (int k = 0; k < KC; k++) {
            float cc[4], qq[4];
#pragma unroll
            for (int i = 0; i < 4; i++) cc[i] = Cs[ty * 4 + i][k];
#pragma unroll
            for (int j = 0; j < 4; j++) qq[j] = Qs[tx * 4 + j][k];
#pragma unroll
            for (int i = 0; i < 4; i++)
#pragma unroll
                for (int j = 0; j < 4; j++) acc[i][j] += cc[i] * qq[j];
        }
        __syncthreads();
    }
    float* Sb = g_S + (size_t)b * NN * MM;
    float sqv[4];
#pragma unroll
    for (int j = 0; j < 4; j++) sqv[j] = g_sq[b * MM + m0 + tx * 4 + j];
#pragma unroll
    for (int i = 0; i < 4; i++) {
        int n = n0 + ty * 4 + i;
        float scn = g_sc[b * NN + n];
        float4 v;
        v.x = acc[i][0] + scn + sqv[0];
        v.y = acc[i][1] + scn + sqv[1];
        v.z = acc[i][2] + scn + sqv[2];
        v.w = acc[i][3] + scn + sqv[3];
        *(float4*)&Sb[(size_t)n * MM + m0 + tx * 4] = v;
    }
}

// ---------------- kernel 3: row stats (softmax over m, per (b,n)) -----------
__global__ __launch_bounds__(128) void row_stats_kernel() {
    int b = blockIdx.y, n = blockIdx.x;
    int tid = threadIdx.x;
    const float* row = g_S + ((size_t)b * NN + n) * MM;
    float mx = -3.4e38f, sm = 0.f;
    for (int i = tid; i < MM; i += 128) {
        float v = row[i];
        if (v > mx) { sm = sm * __expf(mx - v) + 1.f; mx = v; }
        else        { sm += __expf(v - mx); }
    }
    __shared__ float smm[128], sms[128];
    smm[tid] = mx; sms[tid] = sm;
    __syncthreads();
    for (int off = 64; off; off >>= 1) {
        if (tid < off) {
            float m1 = smm[tid], s1 = sms[tid];
            float m2 = smm[tid + off], s2 = sms[tid + off];
            float Mx = fmaxf(m1, m2);
            sms[tid] = s1 * __expf(m1 - Mx) + s2 * __expf(m2 - Mx);
            smm[tid] = Mx;
        }
        __syncthreads();
    }
    if (tid == 0) {
        g_rmax[b * NN + n] = smm[0];
        g_rinv[b * NN + n] = 1.0f / sms[0];
    }
}

// ---------------- kernel 4: col stats (softmax over n, per (b,m)) -----------
__global__ void col_stats_kernel() {  // blockDim (64,4)
    int b = blockIdx.y, m0 = blockIdx.x * 64;
    int x = threadIdx.x, y = threadIdx.y;
    const float* Sb = g_S + (size_t)b * NN * MM;
    float mx = -3.4e38f, sm = 0.f;
    for (int n = y; n < NN; n += 4) {
        float v = Sb[(size_t)n * MM + m0 + x];
        if (v > mx) { sm = sm * __expf(mx - v) + 1.f; mx = v; }
        else        { sm += __expf(v - mx); }
    }
    __shared__ float smm[4][64], sms[4][64];
    smm[y][x] = mx; sms[y][x] = sm;
    __syncthreads();
    if (y == 0) {
        float Mx = mx, s = sm;
        for (int yy = 1; yy < 4; yy++) {
            float m2 = smm[yy][x], s2 = sms[yy][x];
            float M2 = fmaxf(Mx, m2);
            s = s * __expf(Mx - M2) + s2 * __expf(m2 - M2);
            Mx = M2;
        }
        g_cmax[b * MM + m0 + x] = Mx;
        g_cinv[b * MM + m0 + x] = 1.0f / s;
    }
}

// ------- kernel 5/7: out[b,d,n-tile] = X @ P1^T  (X = Q -> A, X = U -> Bt) --
__global__ __launch_bounds__(256) void gemm_PT_kernel(const float* __restrict__ Qext,
                                                      int useU) {
    __shared__ float Xs[DD][KC + 1];
    __shared__ float Ps[64][KC + 1];
    __shared__ float rm[64];
    int b = blockIdx.y, n0 = blockIdx.x * 64;
    int tid = threadIdx.x;
    const float* Xb = (useU ? (const float*)g_U : Qext) + (size_t)b * DD * MM;
    const float* Sb = g_S + (size_t)b * NN * MM;
    if (tid < 64) rm[tid] = g_rmax[b * NN + n0 + tid];
    __syncthreads();
    int tx = tid & 15, ty = tid >> 4;
    float acc[8][4] = {};

    for (int m0 = 0; m0 < MM; m0 += KC) {
#pragma unroll
        for (int it = 0; it < 16; it++) {
            int idx = tid + it * 256;
            int d = idx >> 5, k = idx & 31;
            Xs[d][k] = Xb[(size_t)d * MM + m0 + k];
        }
#pragma unroll
        for (int it = 0; it < 8; it++) {
            int idx = tid + it * 256;
            int j = idx >> 5, k = idx & 31;
            Ps[j][k] = __expf(Sb[(size_t)(n0 + j) * MM + m0 + k] - rm[j]);
        }
        __syncthreads();
#pragma unroll
        for (int k = 0; k < KC; k++) {
            float q[8], p[4];
#pragma unroll
            for (int i = 0; i < 8; i++) q[i] = Xs[ty * 8 + i][k];
#pragma unroll
            for (int j = 0; j < 4; j++) p[j] = Ps[tx * 4 + j][k];
#pragma unroll
            for (int i = 0; i < 8; i++)
#pragma unroll
                for (int j = 0; j < 4; j++) acc[i][j] += q[i] * p[j];
        }
        __syncthreads();
    }
    float* outp = (useU ? g_Bt : g_A) + (size_t)b * DD * NN;
    float r4[4];
#pragma unroll
    for (int j = 0; j < 4; j++) r4[j] = g_rinv[b * NN + n0 + tx * 4 + j];
#pragma unroll
    for (int i = 0; i < 8; i++) {
        float4 v;
        v.x = acc[i][0] * r4[0];
        v.y = acc[i][1] * r4[1];
        v.z = acc[i][2] * r4[2];
        v.w = acc[i][3] * r4[3];
        *(float4*)&outp[(size_t)(ty * 8 + i) * NN + n0 + tx * 4] = v;
    }
}

// ---------------- kernel 6: U[b,d,m] = C @ P2 (reduce over n) ---------------
__global__ __launch_bounds__(256) void gemm_U_kernel(const float* __restrict__ C) {
    __shared__ float Cs[DD][KC + 1];
    __shared__ float Ps[64][KC + 1];
    __shared__ float cm[64];
    int b = blockIdx.y, m0 = blockIdx.x * 64;
    int tid = threadIdx.x;
    const float* Cb = C + (size_t)b * DD * NN;
    const float* Sb = g_S + (size_t)b * NN * MM;
    if (tid < 64) cm[tid] = g_cmax[b * MM + m0 + tid];
    __syncthreads();
    int tx = tid & 15, ty = tid >> 4;
    float acc[8][4] = {};

    for (int n0 = 0; n0 < NN; n0 += KC) {
#pragma unroll
        for (int it = 0; it < 16; it++) {
            int idx = tid + it * 256;
            int d = idx >> 5, k = idx & 31;
            Cs[d][k] = Cb[(size_t)d * NN + n0 + k];
        }
#pragma unroll
        for (int it = 0; it < 8; it++) {
            int idx = tid + it * 256;
            int jn = idx >> 6, im = idx & 63;   // transpose S tile into [m][n]
            Ps[im][jn] = __expf(Sb[(size_t)(n0 + jn) * MM + m0 + im] - cm[im]);
        }
        __syncthreads();
#pragma unroll
        for (int k = 0; k < KC; k++) {
            float c8[8], p[4];
#pragma unroll
            for (int i = 0; i < 8; i++) c8[i] = Cs[ty * 8 + i][k];
#pragma unroll
            for (int j = 0; j < 4; j++) p[j] = Ps[tx * 4 + j][k];
#pragma unroll
            for (int i = 0; i < 8; i++)
#pragma unroll
                for (int j = 0; j < 4; j++) acc[i][j] += c8[i] * p[j];
        }
        __syncthreads();
    }
    float ci[4];
#pragma unroll
    for (int j = 0; j < 4; j++) ci[j] = g_cinv[b * MM + m0 + tx * 4 + j];
#pragma unroll
    for (int i = 0; i < 8; i++) {
        float4 v;
        v.x = acc[i][0] * ci[0];
        v.y = acc[i][1] * ci[1];
        v.z = acc[i][2] * ci[2];
        v.w = acc[i][3] * ci[3];
        *(float4*)&g_U[(size_t)b * DD * MM + (size_t)(ty * 8 + i) * MM + m0 + tx * 4] = v;
    }
}

// ---------------- kernel 8: concat + exact jax dropout ----------------------
// JAX >= 0.4.36: jax_threefry_partitionable defaults to True.
// Partitionable path: counter = 64-bit iota; per element i the counter pair is
// (hi32(i), lo32(i)) = (0, i) here; 32-bit draw = out0 ^ out1.
__device__ __forceinline__ float value_at(size_t idx, const float* __restrict__ C) {
    int n = (int)(idx & 2047);
    int r = (int)((idx >> 11) & 511);
    int b = (int)(idx >> 20);
    int c = r & 127, sec = r >> 7;
    size_t off = (((size_t)b * DD + c) << 11) + n;
    float cv = C[off];
    if (sec == 0) return cv;
    if (sec == 1) return g_A[off];
    if (sec == 2) return cv * g_A[off];
    return cv * g_Bt[off];
}

__global__ __launch_bounds__(256) void assemble_kernel(const float* __restrict__ C,
                                                       float* __restrict__ out) {
    const size_t TOTAL = (size_t)BB * 4 * DD * NN;  // 25165824
    size_t i = (size_t)blockIdx.x * 256 + threadIdx.x;
    if (i >= TOTAL) return;
    uint2 rb = threefry_0_42(0u, (uint32_t)i);
    uint32_t bits = rb.x ^ rb.y;
    out[i] = apply_drop(bits, value_at(i, C));
}

// ---------------- warm-up: force module/global load before harness checkpoints
namespace {
struct CudaWarm {
    CudaWarm() {
        void* p = nullptr;
        cudaGetSymbolAddress(&p, g_S);
        cudaGetSymbolAddress(&p, g_A);
        cudaGetSymbolAddress(&p, g_U);
        cudaGetSymbolAddress(&p, g_Bt);
        cudaFuncAttributes a;
        cudaFuncGetAttributes(&a, wsum_kernel);
        cudaFuncGetAttributes(&a, gemm_S_kernel);
        cudaFuncGetAttributes(&a, row_stats_kernel);
        cudaFuncGetAttributes(&a, col_stats_kernel);
        cudaFuncGetAttributes(&a, gemm_PT_kernel);
        cudaFuncGetAttributes(&a, gemm_U_kernel);
        cudaFuncGetAttributes(&a, assemble_kernel);
    }
} g_cuda_warm;
}

// ---------------- launch ----------------------------------------------------
extern "C" void kernel_launch(void* const* d_in, const int* in_sizes, int n_in,
                              void* d_out, int out_size) {
    const float* C = (const float*)d_in[0];
    const float* Q = (const float*)d_in[1];
    const float* W = (const float*)d_in[2];
    float* out = (float*)d_out;

    wsum_kernel<<<dim3(MM / 256, BB, 2), 256>>>(Q, C, W);
    gemm_S_kernel<<<dim3(MM / 64, NN / 64, BB), 256>>>(C, Q, W);
    row_stats_kernel<<<dim3(NN, BB), 128>>>();
    col_stats_kernel<<<dim3(MM / 64, BB), dim3(64, 4)>>>();
    gemm_PT_kernel<<<dim3(NN / 64, BB), 256>>>(Q, 0);   // A  = Q @ S1^T
    gemm_U_kernel<<<dim3(MM / 64, BB), 256>>>(C);       // U  = C @ S2
    gemm_PT_kernel<<<dim3(NN / 64, BB), 256>>>(Q, 1);   // Bt = U @ S1^T
    assemble_kernel<<<dim3(98304), 256>>>(C, out);
}

// round 5
// speedup vs baseline: 1.4912x; 1.4912x over previous
#include <cuda_runtime.h>
#include <cstdint>

#define BB 24
#define DD 128
#define NN 2048
#define MM 2048

typedef unsigned long long u64;

// ---------------- packed f32x2 helpers (sm_103a FFMA2) ----------------------
__device__ __forceinline__ u64 pk2(float lo, float hi) {
    u64 r; asm("mov.b64 %0,{%1,%2};" : "=l"(r) : "f"(lo), "f"(hi)); return r;
}
__device__ __forceinline__ float2 up2(u64 v) {
    float2 r; asm("mov.b64 {%0,%1},%2;" : "=f"(r.x), "=f"(r.y) : "l"(v)); return r;
}
__device__ __forceinline__ void fma2(u64& d, u64 a, u64 b) {
    asm("fma.rn.f32x2 %0,%1,%2,%0;" : "+l"(d) : "l"(a), "l"(b));
}

// ---------------- scratch (device globals; no runtime allocation) ----------
__device__ float g_S [(size_t)BB * NN * MM];   // 402 MB
__device__ float g_U [(size_t)BB * DD * MM];   // U = C @ P2
__device__ float g_sq  [BB * MM];
__device__ float g_sc  [BB * NN];
__device__ float g_rmax[BB * NN];
__device__ float g_rinv[BB * NN];
__device__ float g_cmax[BB * MM];
__device__ float g_cinv[BB * MM];

// ---------------- threefry2x32 (partitionable, key(42), bit-exact) ----------
__device__ __forceinline__ void tf_round(uint32_t& x0, uint32_t& x1, int r) {
    x0 += x1;
    x1 = (x1 << r) | (x1 >> (32 - r));
    x1 ^= x0;
}
__device__ __forceinline__ uint32_t tf_bits(uint32_t i) {
    const uint32_t ks0 = 0u, ks1 = 42u, ks2 = 0x1BD11BDAu ^ 0u ^ 42u;
    uint32_t x0 = 0u + ks0, x1 = i + ks1;
    tf_round(x0, x1, 13); tf_round(x0, x1, 15); tf_round(x0, x1, 26); tf_round(x0, x1, 6);
    x0 += ks1; x1 += ks2 + 1u;
    tf_round(x0, x1, 17); tf_round(x0, x1, 29); tf_round(x0, x1, 16); tf_round(x0, x1, 24);
    x0 += ks2; x1 += ks0 + 2u;
    tf_round(x0, x1, 13); tf_round(x0, x1, 15); tf_round(x0, x1, 26); tf_round(x0, x1, 6);
    x0 += ks0; x1 += ks1 + 3u;
    tf_round(x0, x1, 17); tf_round(x0, x1, 29); tf_round(x0, x1, 16); tf_round(x0, x1, 24);
    x0 += ks1; x1 += ks2 + 4u;
    tf_round(x0, x1, 13); tf_round(x0, x1, 15); tf_round(x0, x1, 26); tf_round(x0, x1, 6);
    x0 += ks2; x1 += ks0 + 5u;
    return x0 ^ x1;
}
__device__ __forceinline__ float apply_drop(uint32_t bits, float v) {
    float u = __uint_as_float((bits >> 9) | 0x3f800000u) - 1.0f;
    return (u < 0.9f) ? v * (1.0f / 0.9f) : 0.0f;
}

// ---------------- kernel 1: sq[b,m] = Wq.Q ; sc[b,n] = Wc.C -----------------
__global__ __launch_bounds__(256) void wsum_kernel(const float* __restrict__ Q,
                                                   const float* __restrict__ C,
                                                   const float* __restrict__ W) {
    int b = blockIdx.y;
    int which = blockIdx.z;
    int m = blockIdx.x * 256 + threadIdx.x;
    const float* X = which ? C : Q;
    const float* w = W + b * (3 * DD) + (which ? DD : 0);
    const float* xb = X + (size_t)b * DD * MM + m;
    float s = 0.f;
#pragma unroll 8
    for (int d = 0; d < DD; d++) s += w[d] * xb[(size_t)d * MM];
    if (which) g_sc[b * NN + m] = s;
    else       g_sq[b * MM + m] = s;
}

// ---------------- kernel 2: S = (C*Wm)^T Q + sc + sq  (128x128, FFMA2) ------
__global__ __launch_bounds__(256, 2) void gemm_S_kernel(const float* __restrict__ C,
                                                        const float* __restrict__ Q,
                                                        const float* __restrict__ W) {
    __shared__ float Cs[16][128];
    __shared__ float Qs[16][128];
    __shared__ float wm[128];
    int b = blockIdx.z, n0 = blockIdx.y * 128, m0 = blockIdx.x * 128;
    int tid = threadIdx.x;
    if (tid < 128) wm[tid] = W[b * 384 + 256 + tid];
    __syncthreads();
    int tx = tid & 15, ty = tid >> 4;
    const float* Cb = C + (size_t)b * DD * NN;
    const float* Qb = Q + (size_t)b * DD * MM;
    u64 acc[8][4];
#pragma unroll
    for (int i = 0; i < 8; i++)
#pragma unroll
        for (int j = 0; j < 4; j++) acc[i][j] = 0ull;

    for (int d0 = 0; d0 < DD; d0 += 16) {
#pragma unroll
        for (int it = 0; it < 2; it++) {
            int f = tid + it * 256;
            int r = f >> 5, c = (f & 31) << 2;
            float4 cv = *(const float4*)&Cb[(size_t)(d0 + r) * NN + n0 + c];
            float w = wm[d0 + r];
            cv.x *= w; cv.y *= w; cv.z *= w; cv.w *= w;
            *(float4*)&Cs[r][c] = cv;
            *(float4*)&Qs[r][c] = *(const float4*)&Qb[(size_t)(d0 + r) * MM + m0 + c];
        }
        __syncthreads();
#pragma unroll
        for (int k = 0; k < 16; k++) {
            float4 qa = *(const float4*)&Qs[k][tx * 4];
            float4 qb = *(const float4*)&Qs[k][64 + tx * 4];
            float4 ca = *(const float4*)&Cs[k][ty * 4];
            float4 cb = *(const float4*)&Cs[k][64 + ty * 4];
            u64 q0 = pk2(qa.x, qa.y), q1 = pk2(qa.z, qa.w);
            u64 q2 = pk2(qb.x, qb.y), q3 = pk2(qb.z, qb.w);
            float cr[8] = {ca.x, ca.y, ca.z, ca.w, cb.x, cb.y, cb.z, cb.w};
#pragma unroll
            for (int i = 0; i < 8; i++) {
                u64 cd = pk2(cr[i], cr[i]);
                fma2(acc[i][0], cd, q0); fma2(acc[i][1], cd, q1);
                fma2(acc[i][2], cd, q2); fma2(acc[i][3], cd, q3);
            }
        }
        __syncthreads();
    }
    float* Sb = g_S + (size_t)b * NN * MM;
    float4 sqa = *(const float4*)&g_sq[b * MM + m0 + tx * 4];
    float4 sqb = *(const float4*)&g_sq[b * MM + m0 + 64 + tx * 4];
#pragma unroll
    for (int i = 0; i < 8; i++) {
        int n = n0 + ((i < 4) ? (ty * 4 + i) : (64 + ty * 4 + i - 4));
        float scn = g_sc[b * NN + n];
        float2 p0 = up2(acc[i][0]), p1 = up2(acc[i][1]);
        float2 p2 = up2(acc[i][2]), p3 = up2(acc[i][3]);
        float4 v0 = {p0.x + scn + sqa.x, p0.y + scn + sqa.y,
                     p1.x + scn + sqa.z, p1.y + scn + sqa.w};
        float4 v1 = {p2.x + scn + sqb.x, p2.y + scn + sqb.y,
                     p3.x + scn + sqb.z, p3.y + scn + sqb.w};
        *(float4*)&Sb[(size_t)n * MM + m0 + tx * 4] = v0;
        *(float4*)&Sb[(size_t)n * MM + m0 + 64 + tx * 4] = v1;
    }
}

// ---------------- kernel 3: row stats (softmax over m) ----------------------
#define ONLINE_UPD(v)                                              \
    do { float _v = (v);                                           \
         if (_v > mx) { sm = sm * __expf(mx - _v) + 1.f; mx = _v; }\
         else         { sm += __expf(_v - mx); } } while (0)

__global__ __launch_bounds__(128) void row_stats_kernel() {
    int b = blockIdx.y, n = blockIdx.x, tid = threadIdx.x;
    const float4* row = (const float4*)(g_S + ((size_t)b * NN + n) * MM);
    float mx = -3.4e38f, sm = 0.f;
#pragma unroll
    for (int it = 0; it < 4; it++) {
        float4 v = row[tid + it * 128];
        ONLINE_UPD(v.x); ONLINE_UPD(v.y); ONLINE_UPD(v.z); ONLINE_UPD(v.w);
    }
    __shared__ float smm[128], sms[128];
    smm[tid] = mx; sms[tid] = sm;
    __syncthreads();
    for (int off = 64; off; off >>= 1) {
        if (tid < off) {
            float m1 = smm[tid], s1 = sms[tid];
            float m2 = smm[tid + off], s2 = sms[tid + off];
            float Mx = fmaxf(m1, m2);
            sms[tid] = s1 * __expf(m1 - Mx) + s2 * __expf(m2 - Mx);
            smm[tid] = Mx;
        }
        __syncthreads();
    }
    if (tid == 0) {
        g_rmax[b * NN + n] = smm[0];
        g_rinv[b * NN + n] = 1.0f / sms[0];
    }
}

// ---------------- kernel 4: col stats (softmax over n), vectorized ----------
__global__ __launch_bounds__(256) void col_stats_kernel() {
    int b = blockIdx.y, m0 = blockIdx.x * 128;
    int tid = threadIdx.x;
    int x = tid & 31, y = tid >> 5;
    const float* Sb = g_S + (size_t)b * NN * MM;
    float mxa[4] = {-3.4e38f, -3.4e38f, -3.4e38f, -3.4e38f};
    float sma[4] = {0.f, 0.f, 0.f, 0.f};
#pragma unroll 4
    for (int n = y; n < NN; n += 8) {
        float4 v = *(const float4*)&Sb[(size_t)n * MM + m0 + x * 4];
        float vv[4] = {v.x, v.y, v.z, v.w};
#pragma unroll
        for (int c = 0; c < 4; c++) {
            float mx = mxa[c], sm = sma[c];
            ONLINE_UPD(vv[c]);
            mxa[c] = mx; sma[c] = sm;
        }
    }
    __shared__ float4 rmx[256], rsm[256];
    rmx[tid] = make_float4(mxa[0], mxa[1], mxa[2], mxa[3]);
    rsm[tid] = make_float4(sma[0], sma[1], sma[2], sma[3]);
    __syncthreads();
    for (int off = 128; off >= 32; off >>= 1) {
        if (tid < off) {
            float4 m1 = rmx[tid], s1 = rsm[tid];
            float4 m2 = rmx[tid + off], s2 = rsm[tid + off];
            float4 M, S;
            M.x = fmaxf(m1.x, m2.x); S.x = s1.x * __expf(m1.x - M.x) + s2.x * __expf(m2.x - M.x);
            M.y = fmaxf(m1.y, m2.y); S.y = s1.y * __expf(m1.y - M.y) + s2.y * __expf(m2.y - M.y);
            M.z = fmaxf(m1.z, m2.z); S.z = s1.z * __expf(m1.z - M.z) + s2.z * __expf(m2.z - M.z);
            M.w = fmaxf(m1.w, m2.w); S.w = s1.w * __expf(m1.w - M.w) + s2.w * __expf(m2.w - M.w);
            rmx[tid] = M; rsm[tid] = S;
        }
        __syncthreads();
    }
    if (tid < 32) {
        float4 M = rmx[tid], S = rsm[tid];
        *(float4*)&g_cmax[b * MM + m0 + tid * 4] = M;
        float4 I = {1.0f / S.x, 1.0f / S.y, 1.0f / S.z, 1.0f / S.w};
        *(float4*)&g_cinv[b * MM + m0 + tid * 4] = I;
    }
}

// ---------------- kernel 5: U[b,d,m] = C @ P2  (128x64, FFMA2) --------------
__global__ __launch_bounds__(256, 2) void gemm_U_kernel(const float* __restrict__ C) {
    __shared__ float Ps[16][68];
    __shared__ float Cs[16][132];
    __shared__ float cmv[64], civ[64];
    int b = blockIdx.y, m0 = blockIdx.x * 64;
    int tid = threadIdx.x;
    if (tid < 64) {
        cmv[tid] = g_cmax[b * MM + m0 + tid];
        civ[tid] = g_cinv[b * MM + m0 + tid];
    }
    __syncthreads();
    int tx = tid & 15, ty = tid >> 4;
    const float* Cb = C + (size_t)b * DD * NN;
    const float* Sb = g_S + (size_t)b * NN * MM;
    u64 acc[8][2];
#pragma unroll
    for (int i = 0; i < 8; i++) { acc[i][0] = 0ull; acc[i][1] = 0ull; }

    for (int n0 = 0; n0 < NN; n0 += 16) {
        {
            int r = tid >> 4, c = (tid & 15) << 2;
            float4 sv = *(const float4*)&Sb[(size_t)(n0 + r) * MM + m0 + c];
            float4 e;
            e.x = __expf(sv.x - cmv[c]);     e.y = __expf(sv.y - cmv[c + 1]);
            e.z = __expf(sv.z - cmv[c + 2]); e.w = __expf(sv.w - cmv[c + 3]);
            *(float4*)&Ps[r][c] = e;
        }
#pragma unroll
        for (int it = 0; it < 2; it++) {
            int f = tid + it * 256;
            int d = f >> 2, n4 = (f & 3) << 2;
            float4 cv = *(const float4*)&Cb[(size_t)d * NN + n0 + n4];
            Cs[n4][d] = cv.x; Cs[n4 + 1][d] = cv.y;
            Cs[n4 + 2][d] = cv.z; Cs[n4 + 3][d] = cv.w;
        }
        __syncthreads();
#pragma unroll
        for (int k = 0; k < 16; k++) {
            float4 pv = *(const float4*)&Ps[k][tx * 4];
            u64 p0 = pk2(pv.x, pv.y), p1 = pk2(pv.z, pv.w);
            float4 ca = *(const float4*)&Cs[k][ty * 4];
            float4 cb = *(const float4*)&Cs[k][64 + ty * 4];
            float cr[8] = {ca.x, ca.y, ca.z, ca.w, cb.x, cb.y, cb.z, cb.w};
#pragma unroll
            for (int i = 0; i < 8; i++) {
                u64 cd = pk2(cr[i], cr[i]);
                fma2(acc[i][0], cd, p0); fma2(acc[i][1], cd, p1);
            }
        }
        __syncthreads();
    }
    float4 cv4 = {civ[tx * 4], civ[tx * 4 + 1], civ[tx * 4 + 2], civ[tx * 4 + 3]};
#pragma unroll
    for (int i = 0; i < 8; i++) {
        int d = (i < 4) ? (ty * 4 + i) : (64 + ty * 4 + i - 4);
        float2 p0 = up2(acc[i][0]), p1 = up2(acc[i][1]);
        float4 v = {p0.x * cv4.x, p0.y * cv4.y, p1.x * cv4.z, p1.y * cv4.w};
        *(float4*)&g_U[(size_t)b * DD * MM + (size_t)d * MM + m0 + tx * 4] = v;
    }
}

// ------- kernel 6: A = Q@P1^T, Bt = U@P1^T, fused output + dropout ----------
__global__ __launch_bounds__(256, 2) void gemm_AB_kernel(const float* __restrict__ Q,
                                                         const float* __restrict__ C,
                                                         float* __restrict__ out) {
    __shared__ float Ps[16][68];
    __shared__ float Xq[16][132];
    __shared__ float Xu[16][132];
    __shared__ float rmv[64], riv[64];
    int b = blockIdx.y, n0 = blockIdx.x * 64;
    int tid = threadIdx.x;
    if (tid < 64) {
        rmv[tid] = g_rmax[b * NN + n0 + tid];
        riv[tid] = g_rinv[b * NN + n0 + tid];
    }
    __syncthreads();
    int tx = tid & 15, ty = tid >> 4;
    const float* Qb = Q + (size_t)b * DD * MM;
    const float* Ub = g_U + (size_t)b * DD * MM;
    const float* Sb = g_S + (size_t)b * NN * MM;
    u64 aA[8][2], aB[8][2];
#pragma unroll
    for (int i = 0; i < 8; i++) { aA[i][0] = aA[i][1] = 0ull; aB[i][0] = aB[i][1] = 0ull; }

    for (int m0 = 0; m0 < MM; m0 += 16) {
        {
            int n = tid >> 2, m4 = (tid & 3) << 2;
            float4 sv = *(const float4*)&Sb[(size_t)(n0 + n) * MM + m0 + m4];
            float rm = rmv[n];
            Ps[m4][n]     = __expf(sv.x - rm);
            Ps[m4 + 1][n] = __expf(sv.y - rm);
            Ps[m4 + 2][n] = __expf(sv.z - rm);
            Ps[m4 + 3][n] = __expf(sv.w - rm);
        }
#pragma unroll
        for (int it = 0; it < 2; it++) {
            int f = tid + it * 256;
            int d = f >> 2, m4 = (f & 3) << 2;
            float4 qv = *(const float4*)&Qb[(size_t)d * MM + m0 + m4];
            Xq[m4][d] = qv.x; Xq[m4 + 1][d] = qv.y;
            Xq[m4 + 2][d] = qv.z; Xq[m4 + 3][d] = qv.w;
            float4 uv = *(const float4*)&Ub[(size_t)d * MM + m0 + m4];
            Xu[m4][d] = uv.x; Xu[m4 + 1][d] = uv.y;
            Xu[m4 + 2][d] = uv.z; Xu[m4 + 3][d] = uv.w;
        }
        __syncthreads();
#pragma unroll
        for (int k = 0; k < 16; k++) {
            float4 pv = *(const float4*)&Ps[k][tx * 4];
            u64 p0 = pk2(pv.x, pv.y), p1 = pk2(pv.z, pv.w);
            float4 qa = *(const float4*)&Xq[k][ty * 4];
            float4 qb = *(const float4*)&Xq[k][64 + ty * 4];
            float4 ua = *(const float4*)&Xu[k][ty * 4];
            float4 ub = *(const float4*)&Xu[k][64 + ty * 4];
            float qr[8] = {qa.x, qa.y, qa.z, qa.w, qb.x, qb.y, qb.z, qb.w};
            float ur[8] = {ua.x, ua.y, ua.z, ua.w, ub.x, ub.y, ub.z, ub.w};
#pragma unroll
            for (int i = 0; i < 8; i++) {
                u64 qd = pk2(qr[i], qr[i]);
                fma2(aA[i][0], qd, p0); fma2(aA[i][1], qd, p1);
                u64 ud = pk2(ur[i], ur[i]);
                fma2(aB[i][0], ud, p0); fma2(aB[i][1], ud, p1);
            }
        }
        __syncthreads();
    }
    // epilogue: build all 4 output sections for (d, n) tile, with exact dropout
    const float* Cb = C + (size_t)b * DD * NN;
    float4 rv = {riv[tx * 4], riv[tx * 4 + 1], riv[tx * 4 + 2], riv[tx * 4 + 3]};
#pragma unroll
    for (int i = 0; i < 8; i++) {
        int d = (i < 4) ? (ty * 4 + i) : (64 + ty * 4 + i - 4);
        float2 a0 = up2(aA[i][0]), a1 = up2(aA[i][1]);
        float2 b0 = up2(aB[i][0]), b1 = up2(aB[i][1]);
        float4 av = {a0.x * rv.x, a0.y * rv.y, a1.x * rv.z, a1.y * rv.w};
        float4 bv = {b0.x * rv.x, b0.y * rv.y, b1.x * rv.z, b1.y * rv.w};
        float4 cv = *(const float4*)&Cb[(size_t)d * NN + n0 + tx * 4];
        float4 secs[4];
        secs[0] = cv;
        secs[1] = av;
        secs[2] = make_float4(cv.x * av.x, cv.y * av.y, cv.z * av.z, cv.w * av.w);
        secs[3] = make_float4(cv.x * bv.x, cv.y * bv.y, cv.z * bv.z, cv.w * bv.w);
#pragma unroll
        for (int s = 0; s < 4; s++) {
            uint32_t base = (uint32_t)(((b * 512 + s * 128 + d) << 11) + n0 + tx * 4);
            float4 o;
            o.x = apply_drop(tf_bits(base + 0), secs[s].x);
            o.y = apply_drop(tf_bits(base + 1), secs[s].y);
            o.z = apply_drop(tf_bits(base + 2), secs[s].z);
            o.w = apply_drop(tf_bits(base + 3), secs[s].w);
            *(float4*)&out[base] = o;
        }
    }
}

// ---------------- warm-up: force module/global load before harness checkpoints
namespace {
struct CudaWarm {
    CudaWarm() {
        void* p = nullptr;
        cudaGetSymbolAddress(&p, g_S);
        cudaGetSymbolAddress(&p, g_U);
        cudaFuncAttributes a;
        cudaFuncGetAttributes(&a, wsum_kernel);
        cudaFuncGetAttributes(&a, gemm_S_kernel);
        cudaFuncGetAttributes(&a, row_stats_kernel);
        cudaFuncGetAttributes(&a, col_stats_kernel);
        cudaFuncGetAttributes(&a, gemm_U_kernel);
        cudaFuncGetAttributes(&a, gemm_AB_kernel);
    }
} g_cuda_warm;
}

// ---------------- launch ----------------------------------------------------
extern "C" void kernel_launch(void* const* d_in, const int* in_sizes, int n_in,
                              void* d_out, int out_size) {
    const float* C = (const float*)d_in[0];
    const float* Q = (const float*)d_in[1];
    const float* W = (const float*)d_in[2];
    float* out = (float*)d_out;

    wsum_kernel<<<dim3(MM / 256, BB, 2), 256>>>(Q, C, W);
    gemm_S_kernel<<<dim3(MM / 128, NN / 128, BB), 256>>>(C, Q, W);
    row_stats_kernel<<<dim3(NN, BB), 128>>>();
    col_stats_kernel<<<dim3(MM / 128, BB), 256>>>();
    gemm_U_kernel<<<dim3(MM / 64, BB), 256>>>(C);
    gemm_AB_kernel<<<dim3(NN / 64, BB), 256>>>(Q, C, out);
}